// round 13
// baseline (speedup 1.0000x reference)
#include <cuda_runtime.h>
#include <math.h>

// Problem constants (fixed shapes for this problem instance)
#define B_N   256
#define D_N   4096
#define T_N   19
#define NTHR  256
#define PER   (D_N / NTHR)   // 16 elements per thread
#define NWORDS (D_N / 32)    // 128 bitmask words per row

// Scratch: grad_x[B,D] passed from GEMM to sampler (static device array; no runtime alloc)
__device__ float g_grad[B_N * D_N];

// ---------------------------------------------------------------------------
// Kernel 1: grad = x @ W + b      (x:[B,D] row-major, W:[D,D] symmetric row-major)
// grad[m,n] = sum_k x[m,k] * W[k,n] + b[n]
// BM=64, BN=128, BK=16, 256 threads, 4x8 register tile, cp.async double buffer.
// A tile padded to BK+4 floats/row: row stride 80 B (16B-aligned, cp.async-legal)
// and rows i / i+4 hit distinct banks -> conflict-free A reads.
// ---------------------------------------------------------------------------
#define BM 64
#define BN 128
#define BK 16
#define BKP (BK + 4)
#define TM 4
#define TN 8

__device__ __forceinline__ void cp_async16(void* smem_dst, const void* gmem_src) {
    unsigned saddr = (unsigned)__cvta_generic_to_shared(smem_dst);
    asm volatile("cp.async.cg.shared.global [%0], [%1], 16;\n"
                 :: "r"(saddr), "l"(gmem_src));
}
__device__ __forceinline__ void cp_async_commit() {
    asm volatile("cp.async.commit_group;\n" ::: "memory");
}
__device__ __forceinline__ void cp_async_wait_all() {
    asm volatile("cp.async.wait_group 0;\n" ::: "memory");
}

__global__ __launch_bounds__(256, 1)
void gemm_grad(const float* __restrict__ X, const float* __restrict__ W,
               const float* __restrict__ bias)
{
    __shared__ float As[2][BM][BKP];  // 2 x 5 KB, padded rows
    __shared__ float Bs[2][BK][BN];   // 2 x 8 KB

    const int bn  = blockIdx.x * BN;
    const int bm  = blockIdx.y * BM;
    const int tid = threadIdx.x;
    const int tx  = tid & 15;   // 16 thread-cols
    const int ty  = tid >> 4;   // 16 thread-rows

    float acc[TM][TN];
#pragma unroll
    for (int i = 0; i < TM; ++i)
#pragma unroll
        for (int j = 0; j < TN; ++j) acc[i][j] = 0.f;

    // A tile (64x16): 4 float4 per row, 256 float4 -> one per thread.
    const int a_r = tid >> 2;          // 0..63
    const int a_c = (tid & 3) * 4;     // 0,4,8,12
    // B tile (16x128): 32 float4 per row, 512 -> 2 per thread.
    const int b_r0 = tid >> 5;         // 0..7
    const int b_c0 = (tid & 31) * 4;   // 0..124

    // Prefetch tile 0 into buffer 0
    cp_async16(&As[0][a_r][a_c], &X[(size_t)(bm + a_r) * D_N + a_c]);
#pragma unroll
    for (int l = 0; l < 2; ++l) {
        int r = b_r0 + l * 8;
        cp_async16(&Bs[0][r][b_c0], &W[(size_t)r * D_N + (bn + b_c0)]);
    }
    cp_async_commit();

    int buf = 0;
    for (int k0 = 0; k0 < D_N; k0 += BK, buf ^= 1) {
        cp_async_wait_all();
        __syncthreads();

        int kn = k0 + BK;
        if (kn < D_N) {   // issue next tile into other buffer
            cp_async16(&As[buf ^ 1][a_r][a_c], &X[(size_t)(bm + a_r) * D_N + (kn + a_c)]);
#pragma unroll
            for (int l = 0; l < 2; ++l) {
                int r = b_r0 + l * 8;
                cp_async16(&Bs[buf ^ 1][r][b_c0], &W[(size_t)(kn + r) * D_N + (bn + b_c0)]);
            }
            cp_async_commit();
        }

#pragma unroll
        for (int kk = 0; kk < BK; ++kk) {
            float a[TM];
#pragma unroll
            for (int i = 0; i < TM; ++i) a[i] = As[buf][ty * TM + i][kk];
            float4 b40 = *reinterpret_cast<const float4*>(&Bs[buf][kk][tx * TN]);
            float4 b41 = *reinterpret_cast<const float4*>(&Bs[buf][kk][tx * TN + 4]);
            float bb[TN] = {b40.x, b40.y, b40.z, b40.w, b41.x, b41.y, b41.z, b41.w};
#pragma unroll
            for (int i = 0; i < TM; ++i)
#pragma unroll
                for (int j = 0; j < TN; ++j)
                    acc[i][j] = fmaf(a[i], bb[j], acc[i][j]);
        }
        __syncthreads();
    }

#pragma unroll
    for (int i = 0; i < TM; ++i) {
        int row = bm + ty * TM + i;
#pragma unroll
        for (int j = 0; j < TN; ++j) {
            int col = bn + tx * TN + j;
            g_grad[(size_t)row * D_N + col] = acc[i][j] + bias[col];
        }
    }
}

// ---------------------------------------------------------------------------
// Kernel 2: per-row MCMC path sampler + MH accept. One CTA per batch row.
//
//  - s_s[i]    = 0.5 * (1-2x_i) * grad_x_i  (grad_x FROZEN — forward sampling logits)
//  - s_grad[i] = live gradient, updated += d*W[p,:] per flip (gives grad_y)
//  - score, Z (forward partition), updated incrementally per flip
//  - steps t >= radius are no-ops in the reference -> skipped entirely
//  - backward pass: undo flips from y in reverse; final undone state == x
// ---------------------------------------------------------------------------
__global__ __launch_bounds__(NTHR, 1)
void sampler(const float* __restrict__ X, const float* __restrict__ W,
             const float* __restrict__ bias, const float* __restrict__ unif,
             const float* __restrict__ u_acc, const int* __restrict__ radius,
             float* __restrict__ out)
{
    __shared__ float s_s[D_N];          // 16 KB
    __shared__ float s_grad[D_N];       // 16 KB
    __shared__ unsigned s_state[NWORDS];
    __shared__ unsigned s_ybits[NWORDS];
    __shared__ int   s_idx[T_N];
    __shared__ float red_a[8], red_b[8], red_c[8];
    __shared__ int   red_i[8];
    __shared__ float sh_Z, sh_score, sh_logfwd, sh_d;
    __shared__ int   sh_p;
    __shared__ int   sh_accept;

    const int row  = blockIdx.x;
    const int tid  = threadIdx.x;
    const int lane = tid & 31;
    const int wid  = tid >> 5;
    const float* xrow = X + (size_t)row * D_N;
    const float* grow = g_grad + (size_t)row * D_N;

    // Build bitmask of x
    if (tid < NWORDS) {
        unsigned w = 0;
        const float* xp = xrow + tid * 32;
#pragma unroll
        for (int k = 0; k < 32; ++k) w |= (xp[k] > 0.5f) ? (1u << k) : 0u;
        s_state[tid] = w;
    }

    // Load grad, build s, and accumulate score_x parts + forward partition Z
    float sum_xg = 0.f, sum_xb = 0.f, sumZ = 0.f;
#pragma unroll
    for (int k = 0; k < PER; ++k) {
        int i = tid + k * NTHR;
        float xv = xrow[i];
        float gv = grow[i];
        s_grad[i] = gv;
        float sv = 0.5f * (1.f - 2.f * xv) * gv;
        s_s[i] = sv;
        sum_xg = fmaf(xv, gv, sum_xg);
        sum_xb = fmaf(xv, bias[i], sum_xb);
        sumZ += expf(sv);
    }
#pragma unroll
    for (int off = 16; off; off >>= 1) {
        sum_xg += __shfl_xor_sync(0xffffffffu, sum_xg, off);
        sum_xb += __shfl_xor_sync(0xffffffffu, sum_xb, off);
        sumZ   += __shfl_xor_sync(0xffffffffu, sumZ,   off);
    }
    if (lane == 0) { red_a[wid] = sum_xg; red_b[wid] = sum_xb; red_c[wid] = sumZ; }
    __syncthreads();
    if (tid == 0) {
        float a = 0.f, bsum = 0.f, c = 0.f;
        for (int w = 0; w < 8; ++w) { a += red_a[w]; bsum += red_b[w]; c += red_c[w]; }
        float score_x = 0.5f * (a + bsum);   // 0.5 x·grad + 0.5 x·b  (grad = Wx + b)
        sh_score  = score_x;                  // running score -> becomes score_y
        sh_logfwd = score_x;                  // log_fwd accumulator starts at score_x
        sh_Z      = c;
    }
    __syncthreads();

    const int rad = radius[row];              // in [1, 19]

    // ---------------- Forward sampling loop (only unmasked steps) ----------------
    for (int t = 0; t < rad; ++t) {
        const float* u = unif + ((size_t)t * B_N + row) * D_N;
        float bestv = -1e30f;
        int   besti = 0;
#pragma unroll
        for (int k = 0; k < PER; ++k) {
            int i = tid + k * NTHR;
            float g = -logf(-logf(u[i]));     // Gumbel noise
            float key = s_s[i] + g;           // logits + gumbel
            if (key > bestv) { bestv = key; besti = i; }  // ascending i keeps first index
        }
#pragma unroll
        for (int off = 16; off; off >>= 1) {
            float ov = __shfl_xor_sync(0xffffffffu, bestv, off);
            int   oi = __shfl_xor_sync(0xffffffffu, besti, off);
            if (ov > bestv || (ov == bestv && oi < besti)) { bestv = ov; besti = oi; }
        }
        if (lane == 0) { red_a[wid] = bestv; red_i[wid] = besti; }
        __syncthreads();
        if (tid == 0) {
            float bv = red_a[0]; int bi = red_i[0];
            for (int w = 1; w < 8; ++w)
                if (red_a[w] > bv || (red_a[w] == bv && red_i[w] < bi)) { bv = red_a[w]; bi = red_i[w]; }
            s_idx[t] = bi;
            // forward log-prob: lf[idx] = s[idx] - logZ (state BEFORE flip)
            float sp = s_s[bi];
            sh_logfwd += sp - logf(sh_Z);
            // incremental Z and s updates for the flip
            sh_Z += expf(-sp) - expf(sp);
            s_s[bi] = -sp;
            int wi2 = bi >> 5;
            unsigned msk = 1u << (bi & 31);
            float d = (s_state[wi2] & msk) ? -1.f : 1.f;   // flip direction
            s_state[wi2] ^= msk;
            // score update with PRE-update gradient at p
            sh_score += d * s_grad[bi] + 0.5f * W[(size_t)bi * D_N + bi];
            sh_p = bi; sh_d = d;
        }
        __syncthreads();
        {   // live-gradient rank-1 update: grad += d * W[p,:] (symmetric: row p)
            const float* wrowp = W + (size_t)sh_p * D_N;
            float d = sh_d;
#pragma unroll
            for (int k = 0; k < PER; ++k) {
                int i = tid + k * NTHR;
                s_grad[i] = fmaf(d, wrowp[i], s_grad[i]);
            }
        }
        __syncthreads();
    }

    // Snapshot y bits; compute backward partition Z_b on state y with grad_y
    if (tid < NWORDS) s_ybits[tid] = s_state[tid];
    float sumZb = 0.f;
#pragma unroll
    for (int k = 0; k < PER; ++k) {
        int i = tid + k * NTHR;
        float bit = (float)((s_state[i >> 5] >> (i & 31)) & 1u);
        float sb = 0.5f * (1.f - 2.f * bit) * s_grad[i];
        sumZb += expf(sb);
    }
#pragma unroll
    for (int off = 16; off; off >>= 1)
        sumZb += __shfl_xor_sync(0xffffffffu, sumZb, off);
    if (lane == 0) red_c[wid] = sumZb;
    __syncthreads();

    // ---------------- Backward pass + accept (serial, cheap) ----------------
    if (tid == 0) {
        float zb = 0.f;
        for (int w = 0; w < 8; ++w) zb += red_c[w];
        float logbwd = sh_score;              // score_y
        for (int t = rad - 1; t >= 0; --t) {
            int p = s_idx[t];
            int wi2 = p >> 5;
            unsigned msk = 1u << (p & 31);
            // current state == state after flip t (traj_b row t); lb[idx] = s_b[p] - logZb
            float db  = (s_state[wi2] & msk) ? -1.f : 1.f;
            float sbp = 0.5f * db * s_grad[p];
            logbwd += sbp - logf(zb);
            // undo flip t -> state after flip t-1
            zb += expf(-sbp) - expf(sbp);
            s_state[wi2] ^= msk;
        }
        // after all undos, s_state == original x bits
        sh_accept = (expf(logbwd - sh_logfwd) >= u_acc[row]) ? 1 : 0;
    }
    __syncthreads();

    // Output: accepted ? y : x
    float* orow = out + (size_t)row * D_N;
    const int acc = sh_accept;
#pragma unroll
    for (int k = 0; k < PER; ++k) {
        int i = tid + k * NTHR;
        unsigned wi2 = i >> 5;
        unsigned msk = 1u << (i & 31);
        unsigned bits = acc ? s_ybits[wi2] : s_state[wi2];
        orow[i] = (bits & msk) ? 1.f : 0.f;
    }
}

// ---------------------------------------------------------------------------
extern "C" void kernel_launch(void* const* d_in, const int* in_sizes, int n_in,
                              void* d_out, int out_size) {
    const float* X      = (const float*)d_in[0];   // x        [B,D]
    const float* W      = (const float*)d_in[1];   // W        [D,D]
    const float* bias   = (const float*)d_in[2];   // b        [D]
    const float* unif   = (const float*)d_in[3];   // unif     [T,B,D]
    const float* u_acc  = (const float*)d_in[4];   // u_accept [B]
    const int*   radius = (const int*)d_in[5];     // radius   [B]
    float* out = (float*)d_out;                    // [B,D]

    (void)in_sizes; (void)n_in; (void)out_size;

    dim3 g1(D_N / BN, B_N / BM);   // (32, 4) = 128 blocks
    gemm_grad<<<g1, 256>>>(X, W, bias);
    sampler<<<B_N, NTHR>>>(X, W, bias, unif, u_acc, radius, out);
}

// round 16
// speedup vs baseline: 1.8572x; 1.8572x over previous
#include <cuda_runtime.h>
#include <cuda_bf16.h>
#include <mma.h>
#include <math.h>

using namespace nvcuda;

// Problem constants (fixed shapes for this problem instance)
#define B_N   256
#define D_N   4096
#define T_N   19
#define NTHR  256
#define PER   (D_N / NTHR)   // 16 elements per thread
#define NWORDS (D_N / 32)    // 128 bitmask words per row

// Static device scratch (no runtime alloc allowed); 16B-aligned for cp.async/float4
__device__ __align__(16) float          g_grad[B_N * D_N];          // 4 MB (grad = x@W)
__device__ __align__(16) __nv_bfloat16  g_Whi[(size_t)D_N * D_N];   // 32 MB
__device__ __align__(16) __nv_bfloat16  g_Wlo[(size_t)D_N * D_N];   // 32 MB
__device__ __align__(16) __nv_bfloat16  g_Xbf[B_N * D_N];           // 2 MB (binary x -> exact bf16)

// ---------------------------------------------------------------------------
// Kernel 0: split-precision conversion.  W = Whi + Wlo (bf16 pair), X -> bf16.
// ---------------------------------------------------------------------------
__global__ void convert_wx(const float* __restrict__ W, const float* __restrict__ X)
{
    const int n4w = (D_N * D_N) / 4;
    const int n4x = (B_N * D_N) / 4;
    const int stride = gridDim.x * blockDim.x;
    for (int i = blockIdx.x * blockDim.x + threadIdx.x; i < n4w; i += stride) {
        float4 w = reinterpret_cast<const float4*>(W)[i];
        __nv_bfloat16 h0 = __float2bfloat16(w.x);
        __nv_bfloat16 h1 = __float2bfloat16(w.y);
        __nv_bfloat16 h2 = __float2bfloat16(w.z);
        __nv_bfloat16 h3 = __float2bfloat16(w.w);
        __nv_bfloat16 l0 = __float2bfloat16(w.x - __bfloat162float(h0));
        __nv_bfloat16 l1 = __float2bfloat16(w.y - __bfloat162float(h1));
        __nv_bfloat16 l2 = __float2bfloat16(w.z - __bfloat162float(h2));
        __nv_bfloat16 l3 = __float2bfloat16(w.w - __bfloat162float(h3));
        size_t o = (size_t)i * 4;
        *reinterpret_cast<__nv_bfloat162*>(&g_Whi[o])     = __nv_bfloat162(h0, h1);
        *reinterpret_cast<__nv_bfloat162*>(&g_Whi[o + 2]) = __nv_bfloat162(h2, h3);
        *reinterpret_cast<__nv_bfloat162*>(&g_Wlo[o])     = __nv_bfloat162(l0, l1);
        *reinterpret_cast<__nv_bfloat162*>(&g_Wlo[o + 2]) = __nv_bfloat162(l2, l3);
    }
    for (int i = blockIdx.x * blockDim.x + threadIdx.x; i < n4x; i += stride) {
        float4 xv = reinterpret_cast<const float4*>(X)[i];
        size_t o = (size_t)i * 4;
        *reinterpret_cast<__nv_bfloat162*>(&g_Xbf[o]) =
            __nv_bfloat162(__float2bfloat16(xv.x), __float2bfloat16(xv.y));
        *reinterpret_cast<__nv_bfloat162*>(&g_Xbf[o + 2]) =
            __nv_bfloat162(__float2bfloat16(xv.z), __float2bfloat16(xv.w));
    }
}

// ---------------------------------------------------------------------------
// Kernel 1: tensor-core GEMM  grad = x @ (Whi + Wlo)   (fp32 accumulate)
// BM=64, BN=128, BK=32, 8 warps; each warp computes a 16x64 strip (4 wmma tiles).
// cp.async double buffer, bf16 smem tiles, ld padded to 16B multiples.
// ---------------------------------------------------------------------------
#define GBM 64
#define GBN 128
#define GBK 32
#define A_LD 40    // 32+8 bf16  (80 B rows: 16B multiple)
#define B_LD 136   // 128+8 bf16 (272 B rows: 16B multiple)

__device__ __forceinline__ void cp_async16(void* smem_dst, const void* gmem_src) {
    unsigned saddr = (unsigned)__cvta_generic_to_shared(smem_dst);
    asm volatile("cp.async.cg.shared.global [%0], [%1], 16;\n"
                 :: "r"(saddr), "l"(gmem_src));
}
__device__ __forceinline__ void cp_async_commit() {
    asm volatile("cp.async.commit_group;\n" ::: "memory");
}
__device__ __forceinline__ void cp_async_wait_all() {
    asm volatile("cp.async.wait_group 0;\n" ::: "memory");
}

__global__ __launch_bounds__(256, 1)
void gemm_tc()
{
    __shared__ __align__(16) __nv_bfloat16 sA [2][GBM * A_LD];   // 2 x 5120 B
    __shared__ __align__(16) __nv_bfloat16 sBh[2][GBK * B_LD];   // 2 x 8704 B
    __shared__ __align__(16) __nv_bfloat16 sBl[2][GBK * B_LD];   // 2 x 8704 B  (44 KB)

    const int bn  = blockIdx.x * GBN;
    const int bm  = blockIdx.y * GBM;
    const int tid = threadIdx.x;
    const int warp = tid >> 5;
    const int wr = warp >> 1;    // 0..3  : 16-row strip
    const int wc = warp & 1;     // 0..1  : 64-col half

    wmma::fragment<wmma::accumulator, 16, 16, 16, float> acc[4];
#pragma unroll
    for (int j = 0; j < 4; ++j) wmma::fill_fragment(acc[j], 0.0f);

    // cp.async mappings
    const int a_r = tid >> 2;            // 0..63
    const int a_c = (tid & 3) * 8;       // bf16 offset 0,8,16,24  (16B chunks)

    // Prefetch tile 0
    cp_async16(&sA[0][a_r * A_LD + a_c], &g_Xbf[(size_t)(bm + a_r) * D_N + a_c]);
#pragma unroll
    for (int l = 0; l < 2; ++l) {
        int idx = tid + l * 256;
        int r = idx >> 4;                // 0..31
        int c = (idx & 15) * 8;          // 0..120
        cp_async16(&sBh[0][r * B_LD + c], &g_Whi[(size_t)r * D_N + bn + c]);
        cp_async16(&sBl[0][r * B_LD + c], &g_Wlo[(size_t)r * D_N + bn + c]);
    }
    cp_async_commit();

    int buf = 0;
    for (int k0 = 0; k0 < D_N; k0 += GBK, buf ^= 1) {
        cp_async_wait_all();
        __syncthreads();

        int kn = k0 + GBK;
        if (kn < D_N) {
            cp_async16(&sA[buf ^ 1][a_r * A_LD + a_c],
                       &g_Xbf[(size_t)(bm + a_r) * D_N + kn + a_c]);
#pragma unroll
            for (int l = 0; l < 2; ++l) {
                int idx = tid + l * 256;
                int r = idx >> 4;
                int c = (idx & 15) * 8;
                cp_async16(&sBh[buf ^ 1][r * B_LD + c], &g_Whi[(size_t)(kn + r) * D_N + bn + c]);
                cp_async16(&sBl[buf ^ 1][r * B_LD + c], &g_Wlo[(size_t)(kn + r) * D_N + bn + c]);
            }
            cp_async_commit();
        }

#pragma unroll
        for (int kk = 0; kk < GBK; kk += 16) {
            wmma::fragment<wmma::matrix_a, 16, 16, 16, __nv_bfloat16, wmma::row_major> fa;
            wmma::load_matrix_sync(fa, &sA[buf][(wr * 16) * A_LD + kk], A_LD);
#pragma unroll
            for (int j = 0; j < 4; ++j) {
                wmma::fragment<wmma::matrix_b, 16, 16, 16, __nv_bfloat16, wmma::row_major> fb;
                wmma::load_matrix_sync(fb, &sBh[buf][kk * B_LD + wc * 64 + j * 16], B_LD);
                wmma::mma_sync(acc[j], fa, fb, acc[j]);
                wmma::load_matrix_sync(fb, &sBl[buf][kk * B_LD + wc * 64 + j * 16], B_LD);
                wmma::mma_sync(acc[j], fa, fb, acc[j]);
            }
        }
        __syncthreads();
    }

#pragma unroll
    for (int j = 0; j < 4; ++j) {
        wmma::store_matrix_sync(&g_grad[(size_t)(bm + wr * 16) * D_N + bn + wc * 64 + j * 16],
                                acc[j], D_N, wmma::mem_row_major);
    }
}

// ---------------------------------------------------------------------------
// Kernel 2: per-row MCMC path sampler + MH accept. One CTA per batch row.
// (grad excludes bias -> added at load time)
// ---------------------------------------------------------------------------
__global__ __launch_bounds__(NTHR, 1)
void sampler(const float* __restrict__ X, const float* __restrict__ W,
             const float* __restrict__ bias, const float* __restrict__ unif,
             const float* __restrict__ u_acc, const int* __restrict__ radius,
             float* __restrict__ out)
{
    __shared__ float s_s[D_N];          // 16 KB
    __shared__ float s_grad[D_N];       // 16 KB
    __shared__ unsigned s_state[NWORDS];
    __shared__ unsigned s_ybits[NWORDS];
    __shared__ int   s_idx[T_N];
    __shared__ float red_a[8], red_b[8], red_c[8];
    __shared__ int   red_i[8];
    __shared__ float sh_Z, sh_score, sh_logfwd, sh_d;
    __shared__ int   sh_p;
    __shared__ int   sh_accept;

    const int row  = blockIdx.x;
    const int tid  = threadIdx.x;
    const int lane = tid & 31;
    const int wid  = tid >> 5;
    const float* xrow = X + (size_t)row * D_N;
    const float* grow = g_grad + (size_t)row * D_N;

    // Build bitmask of x
    if (tid < NWORDS) {
        unsigned w = 0;
        const float* xp = xrow + tid * 32;
#pragma unroll
        for (int k = 0; k < 32; ++k) w |= (xp[k] > 0.5f) ? (1u << k) : 0u;
        s_state[tid] = w;
    }

    // Load grad (+bias), build s, accumulate score_x parts + forward partition Z
    float sum_xg = 0.f, sum_xb = 0.f, sumZ = 0.f;
#pragma unroll
    for (int k = 0; k < PER; ++k) {
        int i = tid + k * NTHR;
        float xv = xrow[i];
        float bv = bias[i];
        float gv = grow[i] + bv;          // grad = x@W + b
        s_grad[i] = gv;
        float sv = 0.5f * (1.f - 2.f * xv) * gv;
        s_s[i] = sv;
        sum_xg = fmaf(xv, gv, sum_xg);
        sum_xb = fmaf(xv, bv, sum_xb);
        sumZ += expf(sv);
    }
#pragma unroll
    for (int off = 16; off; off >>= 1) {
        sum_xg += __shfl_xor_sync(0xffffffffu, sum_xg, off);
        sum_xb += __shfl_xor_sync(0xffffffffu, sum_xb, off);
        sumZ   += __shfl_xor_sync(0xffffffffu, sumZ,   off);
    }
    if (lane == 0) { red_a[wid] = sum_xg; red_b[wid] = sum_xb; red_c[wid] = sumZ; }
    __syncthreads();
    if (tid == 0) {
        float a = 0.f, bsum = 0.f, c = 0.f;
        for (int w = 0; w < 8; ++w) { a += red_a[w]; bsum += red_b[w]; c += red_c[w]; }
        float score_x = 0.5f * (a + bsum);   // 0.5 x·grad + 0.5 x·b
        sh_score  = score_x;
        sh_logfwd = score_x;
        sh_Z      = c;
    }
    __syncthreads();

    const int rad = radius[row];              // in [1, 19]

    // ---------------- Forward sampling loop (only unmasked steps) ----------------
    for (int t = 0; t < rad; ++t) {
        const float* u = unif + ((size_t)t * B_N + row) * D_N;
        float bestv = -1e30f;
        int   besti = 0;
#pragma unroll
        for (int k = 0; k < PER; ++k) {
            int i = tid + k * NTHR;
            float g = -logf(-logf(u[i]));     // Gumbel noise
            float key = s_s[i] + g;
            if (key > bestv) { bestv = key; besti = i; }
        }
#pragma unroll
        for (int off = 16; off; off >>= 1) {
            float ov = __shfl_xor_sync(0xffffffffu, bestv, off);
            int   oi = __shfl_xor_sync(0xffffffffu, besti, off);
            if (ov > bestv || (ov == bestv && oi < besti)) { bestv = ov; besti = oi; }
        }
        if (lane == 0) { red_a[wid] = bestv; red_i[wid] = besti; }
        __syncthreads();
        if (tid == 0) {
            float bv = red_a[0]; int bi = red_i[0];
            for (int w = 1; w < 8; ++w)
                if (red_a[w] > bv || (red_a[w] == bv && red_i[w] < bi)) { bv = red_a[w]; bi = red_i[w]; }
            s_idx[t] = bi;
            float sp = s_s[bi];
            sh_logfwd += sp - logf(sh_Z);
            sh_Z += expf(-sp) - expf(sp);
            s_s[bi] = -sp;
            int wi2 = bi >> 5;
            unsigned msk = 1u << (bi & 31);
            float d = (s_state[wi2] & msk) ? -1.f : 1.f;
            s_state[wi2] ^= msk;
            sh_score += d * s_grad[bi] + 0.5f * W[(size_t)bi * D_N + bi];
            sh_p = bi; sh_d = d;
        }
        __syncthreads();
        {   // live-gradient rank-1 update: grad += d * W[p,:] (symmetric: row p)
            const float* wrowp = W + (size_t)sh_p * D_N;
            float d = sh_d;
#pragma unroll
            for (int k = 0; k < PER; ++k) {
                int i = tid + k * NTHR;
                s_grad[i] = fmaf(d, wrowp[i], s_grad[i]);
            }
        }
        __syncthreads();
    }

    // Snapshot y bits; compute backward partition Z_b on state y with grad_y
    if (tid < NWORDS) s_ybits[tid] = s_state[tid];
    float sumZb = 0.f;
#pragma unroll
    for (int k = 0; k < PER; ++k) {
        int i = tid + k * NTHR;
        float bit = (float)((s_state[i >> 5] >> (i & 31)) & 1u);
        float sb = 0.5f * (1.f - 2.f * bit) * s_grad[i];
        sumZb += expf(sb);
    }
#pragma unroll
    for (int off = 16; off; off >>= 1)
        sumZb += __shfl_xor_sync(0xffffffffu, sumZb, off);
    if (lane == 0) red_c[wid] = sumZb;
    __syncthreads();

    // ---------------- Backward pass + accept (serial, cheap) ----------------
    if (tid == 0) {
        float zb = 0.f;
        for (int w = 0; w < 8; ++w) zb += red_c[w];
        float logbwd = sh_score;              // score_y
        for (int t = rad - 1; t >= 0; --t) {
            int p = s_idx[t];
            int wi2 = p >> 5;
            unsigned msk = 1u << (p & 31);
            float db  = (s_state[wi2] & msk) ? -1.f : 1.f;
            float sbp = 0.5f * db * s_grad[p];
            logbwd += sbp - logf(zb);
            zb += expf(-sbp) - expf(sbp);
            s_state[wi2] ^= msk;
        }
        sh_accept = (expf(logbwd - sh_logfwd) >= u_acc[row]) ? 1 : 0;
    }
    __syncthreads();

    // Output: accepted ? y : x
    float* orow = out + (size_t)row * D_N;
    const int acc = sh_accept;
#pragma unroll
    for (int k = 0; k < PER; ++k) {
        int i = tid + k * NTHR;
        unsigned wi2 = i >> 5;
        unsigned msk = 1u << (i & 31);
        unsigned bits = acc ? s_ybits[wi2] : s_state[wi2];
        orow[i] = (bits & msk) ? 1.f : 0.f;
    }
}

// ---------------------------------------------------------------------------
extern "C" void kernel_launch(void* const* d_in, const int* in_sizes, int n_in,
                              void* d_out, int out_size) {
    const float* X      = (const float*)d_in[0];   // x        [B,D]
    const float* W      = (const float*)d_in[1];   // W        [D,D]
    const float* bias   = (const float*)d_in[2];   // b        [D]
    const float* unif   = (const float*)d_in[3];   // unif     [T,B,D]
    const float* u_acc  = (const float*)d_in[4];   // u_accept [B]
    const int*   radius = (const int*)d_in[5];     // radius   [B]
    float* out = (float*)d_out;                    // [B,D]

    (void)in_sizes; (void)n_in; (void)out_size;

    convert_wx<<<1184, 256>>>(W, X);                 // split W, convert x
    gemm_tc<<<dim3(D_N / GBN, B_N / GBM), 256>>>();
    sampler<<<B_N, NTHR>>>(X, W, bias, unif, u_acc, radius, out);
}